// round 4
// baseline (speedup 1.0000x reference)
#include <cuda_runtime.h>
#include <cuda_bf16.h>
#include <cstdint>
#include <cstddef>

// ---------------------------------------------------------------------------
// LiquidNeuralNetwork (CfC / AutoNCP) — R4
//  * ta/tb gates merged -> 3 gate matrices
//  * per layer: parallel input-part GEMM (f32x2 packed FMA) over all (b,t),
//    then sequential recurrent pass with REGISTER-resident weights
//    (col-pair x 2-way k-split), f32x2 packed math throughout.
// ---------------------------------------------------------------------------

typedef unsigned long long ull;

#define TSTEPS 1024
#define NBATCH 256
#define MROWS  (NBATCH * TSTEPS)

// layer dims
#define U0 135
#define FIN0 128
#define NG0 405
#define NGP0 408
#define KH0 68
#define UP0 136          // 2*KH0

#define U1 89
#define FIN1 135
#define NG1 267
#define NGP1 272
#define KH1 46
#define UP1 92           // 2*KH1

#define U2 32
#define FIN2 89
#define NG2 96
#define NGP2 96
#define KH2 16
#define UP2 32

// ---------------- f32x2 helpers (ptxas won't auto-fuse; inline PTX) --------
__device__ __forceinline__ ull ffma2(ull a, ull b, ull c) {
    ull d; asm("fma.rn.f32x2 %0, %1, %2, %3;" : "=l"(d) : "l"(a), "l"(b), "l"(c));
    return d;
}
__device__ __forceinline__ ull fadd2(ull a, ull b) {
    ull d; asm("add.rn.f32x2 %0, %1, %2;" : "=l"(d) : "l"(a), "l"(b));
    return d;
}
__device__ __forceinline__ ull fdup(float x) {
    ull d; asm("mov.b64 %0, {%1, %1};" : "=l"(d) : "f"(x));
    return d;
}
__device__ __forceinline__ ull fpack(float lo, float hi) {
    ull d; asm("mov.b64 %0, {%1, %2};" : "=l"(d) : "f"(lo), "f"(hi));
    return d;
}
__device__ __forceinline__ float2 funpack(ull v) {
    float2 f; asm("mov.b64 {%0, %1}, %2;" : "=f"(f.x), "=f"(f.y) : "l"(v));
    return f;
}

// ---------------- scratch (device globals; zero-initialized) ---------------
__device__ float g_G0[(size_t)MROWS * NGP0];
__device__ float g_H0[(size_t)MROWS * UP0];
__device__ float g_G1[(size_t)MROWS * NGP1];
__device__ float g_H1[(size_t)MROWS * UP1];
__device__ float g_G2[(size_t)MROWS * NGP2];
__device__ float g_H2[(size_t)MROWS * UP2];

__device__ float g_Wx0[FIN0 * NGP0];
__device__ float g_Wh0[UP0 * NGP0];
__device__ float g_b0[NGP0];
__device__ float g_Wx1[FIN1 * NGP1];
__device__ float g_Wh1[UP1 * NGP1];
__device__ float g_b1[NGP1];
__device__ float g_Wx2[FIN2 * NGP2];
__device__ float g_Wh2[UP2 * NGP2];
__device__ float g_b2[NGP2];
__device__ float g_fcwT[32 * 32];

// ---------------------------------------------------------------------------
// Weight prep (mask fold + ta/tb merge + transpose + pad).
// Gate order n: [0,U)=ff1, [U,2U)=ff2, [2U,3U)=s.
// ---------------------------------------------------------------------------
template<int U, int FIN, int NG, int NGP, int UP>
__global__ void prep_layer(const float* __restrict__ ff1w, const float* __restrict__ ff1b,
                           const float* __restrict__ ff2w, const float* __restrict__ ff2b,
                           const float* __restrict__ taw,  const float* __restrict__ tab,
                           const float* __restrict__ tbw,  const float* __restrict__ tbb,
                           const int*   __restrict__ mask,
                           float* __restrict__ Wx, float* __restrict__ Wh,
                           float* __restrict__ bias) {
    const int C = FIN + U;
    const int stride = gridDim.x * blockDim.x;
    const int g0 = blockIdx.x * blockDim.x + threadIdx.x;

    for (int i = g0; i < FIN * NGP; i += stride) {
        int k = i / NGP, n = i % NGP;
        float v = 0.f;
        if (n < U)          v = ff1w[n * C + k] * (float)mask[n * C + k];
        else if (n < 2 * U) v = ff2w[(n - U) * C + k] * (float)mask[(n - U) * C + k];
        else if (n < NG)    v = taw[(n - 2 * U) * C + k] + tbw[(n - 2 * U) * C + k];
        Wx[i] = v;
    }
    for (int i = g0; i < UP * NGP; i += stride) {
        int k = i / NGP, n = i % NGP;
        float v = 0.f;
        if (k < U) {   // recurrent block of NCP mask is all-ones
            if (n < U)          v = ff1w[n * C + FIN + k];
            else if (n < 2 * U) v = ff2w[(n - U) * C + FIN + k];
            else if (n < NG)    v = taw[(n - 2 * U) * C + FIN + k] + tbw[(n - 2 * U) * C + FIN + k];
        }
        Wh[i] = v;
    }
    for (int i = g0; i < NGP; i += stride) {
        float v = 0.f;
        if (i < U)          v = ff1b[i];
        else if (i < 2 * U) v = ff2b[i - U];
        else if (i < NG)    v = tab[i - 2 * U] + tbb[i - 2 * U];
        bias[i] = v;
    }
}

__global__ void prep_fc(const float* __restrict__ fcw, float* __restrict__ out) {
    int i = threadIdx.x;              // 1024 threads
    int o = i >> 5, k = i & 31;
    out[k * 32 + o] = fcw[o * 32 + k];
}

// ---------------------------------------------------------------------------
// GEMM + bias with packed f32x2 FMA. BM=BN=64, BK=32, 128 threads,
// per-thread tile 4m x 8n (8n = 4 f32x2 pairs). M % 64 == 0 always.
// ---------------------------------------------------------------------------
__global__ __launch_bounds__(128)
void gemm_bias2(const float* __restrict__ A, int lda,
                const float* __restrict__ Bt, int ldb,
                const float* __restrict__ bias,
                float* __restrict__ C, int ldc,
                int N, int K) {
    __shared__ float sA[32][68];
    __shared__ float sB[32][68];
    const int bm = blockIdx.y * 64;
    const int bn = blockIdx.x * 64;
    const int tid = threadIdx.x;
    const int tm = (tid >> 3) << 2;   // 0..60
    const int tn = (tid & 7) << 3;    // 0..56
    ull acc[4][4];
#pragma unroll
    for (int i = 0; i < 4; ++i)
#pragma unroll
        for (int p = 0; p < 4; ++p) acc[i][p] = 0ull;

    for (int k0 = 0; k0 < K; k0 += 32) {
#pragma unroll
        for (int i = 0; i < 4; ++i) {
            int e = tid + i * 128;
            int m = e >> 3, k4 = (e & 7) << 2;
            const float* src = A + (size_t)(bm + m) * lda + k0 + k4;
            float4 v;
            if (k0 + k4 + 3 < K) {
                v = *(const float4*)src;
            } else {
                v.x = (k0 + k4     < K) ? src[0] : 0.f;
                v.y = (k0 + k4 + 1 < K) ? src[1] : 0.f;
                v.z = (k0 + k4 + 2 < K) ? src[2] : 0.f;
                v.w = 0.f;
            }
            sA[k4 + 0][m] = v.x; sA[k4 + 1][m] = v.y;
            sA[k4 + 2][m] = v.z; sA[k4 + 3][m] = v.w;
        }
#pragma unroll
        for (int i = 0; i < 4; ++i) {
            int e = tid + i * 128;
            int kk = e >> 4, n4 = (e & 15) << 2;
            float4 v = make_float4(0.f, 0.f, 0.f, 0.f);
            if (k0 + kk < K && bn + n4 < N)     // N % 4 == 0 for all our calls
                v = *(const float4*)(Bt + (size_t)(k0 + kk) * ldb + bn + n4);
            *(float4*)&sB[kk][n4] = v;
        }
        __syncthreads();
#pragma unroll
        for (int kk = 0; kk < 32; ++kk) {
            float4 a = *(const float4*)&sA[kk][tm];
            ulonglong2 bl = *(const ulonglong2*)&sB[kk][tn];
            ulonglong2 bh = *(const ulonglong2*)&sB[kk][tn + 4];
            ull d0 = fdup(a.x), d1 = fdup(a.y), d2 = fdup(a.z), d3 = fdup(a.w);
            acc[0][0] = ffma2(d0, bl.x, acc[0][0]);
            acc[1][0] = ffma2(d1, bl.x, acc[1][0]);
            acc[2][0] = ffma2(d2, bl.x, acc[2][0]);
            acc[3][0] = ffma2(d3, bl.x, acc[3][0]);
            acc[0][1] = ffma2(d0, bl.y, acc[0][1]);
            acc[1][1] = ffma2(d1, bl.y, acc[1][1]);
            acc[2][1] = ffma2(d2, bl.y, acc[2][1]);
            acc[3][1] = ffma2(d3, bl.y, acc[3][1]);
            acc[0][2] = ffma2(d0, bh.x, acc[0][2]);
            acc[1][2] = ffma2(d1, bh.x, acc[1][2]);
            acc[2][2] = ffma2(d2, bh.x, acc[2][2]);
            acc[3][2] = ffma2(d3, bh.x, acc[3][2]);
            acc[0][3] = ffma2(d0, bh.y, acc[0][3]);
            acc[1][3] = ffma2(d1, bh.y, acc[1][3]);
            acc[2][3] = ffma2(d2, bh.y, acc[2][3]);
            acc[3][3] = ffma2(d3, bh.y, acc[3][3]);
        }
        __syncthreads();
    }
#pragma unroll
    for (int i = 0; i < 4; ++i) {
        float* crow = C + (size_t)(bm + tm + i) * ldc + bn + tn;
#pragma unroll
        for (int p = 0; p < 4; ++p) {
            int n = bn + tn + 2 * p;
            if (n < N) {    // N even -> pair fully valid
                float2 f = funpack(acc[i][p]);
                f.x += bias[n];
                f.y += bias[n + 1];
                *(float2*)(crow + 2 * p) = f;
            }
        }
    }
}

// ---------------------------------------------------------------------------
// Recurrent pass, register-resident weights.
// THREADS = NGP (= 2 halves x NGP/2 col-pairs). Thread (half, cg) holds
// w[KH] f32x2 pairs for cols {2cg, 2cg+1}, k in [half*KH, half*KH+KH).
// h duplicated as f32x2 in SMEM (shd), broadcast LDS.128 per 2-k.
// 2 batch rows per CTA share the weights via independent accumulators.
// ---------------------------------------------------------------------------
template<int U, int NGP, int KH, int THREADS>
__global__ __launch_bounds__(THREADS, 1)
void rec_reg(const float* __restrict__ G, const float* __restrict__ Wg,
             float* __restrict__ H, int ldh) {
    constexpr int P = NGP / 2;
    __shared__ __align__(16) double shd[2][2 * KH];  // duplicated h, zero-padded
    __shared__ __align__(16) ull sred[P][2];         // upper-half partials
    __shared__ float sg[2][NGP];                     // gate pre-activations

    const int tid = threadIdx.x;
    const int half = (tid >= P) ? 1 : 0;
    const int cg = tid - half * P;
    const int n0 = cg * 2;
    const int kbase = half * KH;

    ull w[KH];
#pragma unroll
    for (int j = 0; j < KH; ++j) {
        int k = kbase + j;
        if (k < U) {
            float2 wv = *(const float2*)&Wg[(size_t)k * NGP + n0];
            w[j] = fpack(wv.x, wv.y);
        } else {
            w[j] = 0ull;
        }
    }

    for (int i = tid; i < 4 * KH; i += THREADS)
        ((double*)shd)[i] = 0.0;
    __syncthreads();

    const size_t bb0 = (size_t)blockIdx.x * 2;
    const float* Gp0 = G + bb0 * TSTEPS * NGP + n0;
    float* Hp = H + bb0 * TSTEPS * ldh;
    const size_t GOFF = (size_t)TSTEPS * NGP;   // batch-row stride in G

    for (int t = 0; t < TSTEPS; ++t) {
        float2 ga, gb;
        if (!half) {                       // issued early; consumed post-matvec
            ga = *(const float2*)Gp0;
            gb = *(const float2*)(Gp0 + GOFF);
            Gp0 += NGP;
        }
        ull a0a = 0, a0b = 0, a1a = 0, a1b = 0;
#pragma unroll
        for (int j = 0; j < KH; j += 2) {
            double2 h0p = *(const double2*)&shd[0][kbase + j];
            double2 h1p = *(const double2*)&shd[1][kbase + j];
            a0a = ffma2(w[j],     __double_as_longlong(h0p.x), a0a);
            a1a = ffma2(w[j],     __double_as_longlong(h1p.x), a1a);
            a0b = ffma2(w[j + 1], __double_as_longlong(h0p.y), a0b);
            a1b = ffma2(w[j + 1], __double_as_longlong(h1p.y), a1b);
        }
        ull a0 = fadd2(a0a, a0b);
        ull a1 = fadd2(a1a, a1b);
        if (half) {
            sred[cg][0] = a0;
            sred[cg][1] = a1;
        }
        __syncthreads();
        if (!half) {
            a0 = fadd2(a0, sred[cg][0]);
            a1 = fadd2(a1, sred[cg][1]);
            a0 = fadd2(a0, fpack(ga.x, ga.y));
            a1 = fadd2(a1, fpack(gb.x, gb.y));
            *(float2*)&sg[0][n0] = funpack(a0);
            *(float2*)&sg[1][n0] = funpack(a1);
        }
        __syncthreads();
        for (int i = tid; i < 2 * U; i += THREADS) {
            int bb = (i >= U) ? 1 : 0;
            int u = i - bb * U;
            float g1 = sg[bb][u];
            float g2 = sg[bb][u + U];
            float gs = sg[bb][u + 2 * U];
            float f1 = tanhf(g1), f2 = tanhf(g2);
            float s = 1.f / (1.f + __expf(-gs));
            float hn = f1 + s * (f2 - f1);
            Hp[((size_t)bb * TSTEPS + t) * ldh + u] = hn;
            shd[bb][u] = __longlong_as_double(fdup(hn));
        }
        __syncthreads();
    }
}

// ---------------------------------------------------------------------------
// host side
// ---------------------------------------------------------------------------
static float* dev_addr(const void* sym) {
    void* p = nullptr;
    cudaGetSymbolAddress(&p, sym);
    return (float*)p;
}

extern "C" void kernel_launch(void* const* d_in, const int* in_sizes, int n_in,
                              void* d_out, int out_size) {
    // Resolve input ordering: dict order has mask0 (35505 ints) at index 9,
    // signature order has l1_ff1_w (19936 floats) there.
    int L0 = 1, M0, L1, M1, L2, M2, FCW, FCB;
    if (in_sizes[9] == 19936) {            // signature order
        L1 = 9; L2 = 17; FCW = 25; FCB = 26; M0 = 27; M1 = 28; M2 = 29;
    } else {                               // dict order
        M0 = 9; L1 = 10; M1 = 18; L2 = 19; M2 = 27; FCW = 28; FCB = 29;
    }

    const float* X = (const float*)d_in[0];
    float* OUT = (float*)d_out;

    float* G0 = dev_addr(g_G0); float* H0 = dev_addr(g_H0);
    float* G1 = dev_addr(g_G1); float* H1 = dev_addr(g_H1);
    float* G2 = dev_addr(g_G2); float* H2 = dev_addr(g_H2);
    float* Wx0 = dev_addr(g_Wx0); float* Wh0 = dev_addr(g_Wh0); float* B0 = dev_addr(g_b0);
    float* Wx1 = dev_addr(g_Wx1); float* Wh1 = dev_addr(g_Wh1); float* B1 = dev_addr(g_b1);
    float* Wx2 = dev_addr(g_Wx2); float* Wh2 = dev_addr(g_Wh2); float* B2 = dev_addr(g_b2);
    float* FcT = dev_addr(g_fcwT);

    // ---- weight prep ----
    prep_layer<U0, FIN0, NG0, NGP0, UP0><<<128, 256>>>(
        (const float*)d_in[L0 + 0], (const float*)d_in[L0 + 1],
        (const float*)d_in[L0 + 2], (const float*)d_in[L0 + 3],
        (const float*)d_in[L0 + 4], (const float*)d_in[L0 + 5],
        (const float*)d_in[L0 + 6], (const float*)d_in[L0 + 7],
        (const int*)d_in[M0], Wx0, Wh0, B0);
    prep_layer<U1, FIN1, NG1, NGP1, UP1><<<128, 256>>>(
        (const float*)d_in[L1 + 0], (const float*)d_in[L1 + 1],
        (const float*)d_in[L1 + 2], (const float*)d_in[L1 + 3],
        (const float*)d_in[L1 + 4], (const float*)d_in[L1 + 5],
        (const float*)d_in[L1 + 6], (const float*)d_in[L1 + 7],
        (const int*)d_in[M1], Wx1, Wh1, B1);
    prep_layer<U2, FIN2, NG2, NGP2, UP2><<<64, 256>>>(
        (const float*)d_in[L2 + 0], (const float*)d_in[L2 + 1],
        (const float*)d_in[L2 + 2], (const float*)d_in[L2 + 3],
        (const float*)d_in[L2 + 4], (const float*)d_in[L2 + 5],
        (const float*)d_in[L2 + 6], (const float*)d_in[L2 + 7],
        (const int*)d_in[M2], Wx2, Wh2, B2);
    prep_fc<<<1, 1024>>>((const float*)d_in[FCW], FcT);

    const int MB = MROWS / 64;   // 4096

    // ---- layer 0 ----
    gemm_bias2<<<dim3((NGP0 + 63) / 64, MB), 128>>>(X, FIN0, Wx0, NGP0, B0, G0, NGP0, NGP0, FIN0);
    rec_reg<U0, NGP0, KH0, NGP0><<<NBATCH / 2, NGP0>>>(G0, Wh0, H0, UP0);
    // ---- layer 1 ----
    gemm_bias2<<<dim3((NGP1 + 63) / 64, MB), 128>>>(H0, UP0, Wx1, NGP1, B1, G1, NGP1, NGP1, U0);
    rec_reg<U1, NGP1, KH1, NGP1><<<NBATCH / 2, NGP1>>>(G1, Wh1, H1, UP1);
    // ---- layer 2 ----
    gemm_bias2<<<dim3((NGP2 + 63) / 64, MB), 128>>>(H1, UP1, Wx2, NGP2, B2, G2, NGP2, NGP2, U1);
    rec_reg<U2, NGP2, KH2, NGP2><<<NBATCH / 2, NGP2>>>(G2, Wh2, H2, UP2);
    // ---- final FC (adaptive pool is identity since MOT == OUT) ----
    gemm_bias2<<<dim3(1, MB), 128>>>(H2, UP2, FcT, 32, (const float*)d_in[FCB], OUT, 32, 32, 32);
}

// round 8
// speedup vs baseline: 1.4712x; 1.4712x over previous
#include <cuda_runtime.h>
#include <cuda_bf16.h>
#include <cstdint>
#include <cstddef>

// ---------------------------------------------------------------------------
// LiquidNeuralNetwork (CfC / AutoNCP) — R6 (= R5 resubmit after infra failure)
//  * ta/tb gates merged -> 3 gate matrices
//  * per layer: parallel input-part GEMM (f32x2) over all (b,t), then a
//    sequential recurrent pass with weights split REGISTERS + SMEM
//    (sized to respect the 255/thread and 64K/SM register limits).
// ---------------------------------------------------------------------------

typedef unsigned long long ull;

#define TSTEPS 1024
#define NBATCH 256
#define MROWS  (NBATCH * TSTEPS)

// layer dims
#define U0 135
#define FIN0 128
#define NG0 405
#define NGP0 408
#define UP0 136

#define U1 89
#define FIN1 135
#define NG1 267
#define NGP1 272
#define UP1 96

#define U2 32
#define FIN2 89
#define NG2 96
#define NGP2 96
#define UP2 32

// ---------------- f32x2 helpers (ptxas won't auto-fuse; inline PTX) --------
__device__ __forceinline__ ull ffma2(ull a, ull b, ull c) {
    ull d; asm("fma.rn.f32x2 %0, %1, %2, %3;" : "=l"(d) : "l"(a), "l"(b), "l"(c));
    return d;
}
__device__ __forceinline__ ull fadd2(ull a, ull b) {
    ull d; asm("add.rn.f32x2 %0, %1, %2;" : "=l"(d) : "l"(a), "l"(b));
    return d;
}
__device__ __forceinline__ ull fdup(float x) {
    ull d; asm("mov.b64 %0, {%1, %1};" : "=l"(d) : "f"(x));
    return d;
}
__device__ __forceinline__ ull fpack(float lo, float hi) {
    ull d; asm("mov.b64 %0, {%1, %2};" : "=l"(d) : "f"(lo), "f"(hi));
    return d;
}
__device__ __forceinline__ float2 funpack(ull v) {
    float2 f; asm("mov.b64 {%0, %1}, %2;" : "=f"(f.x), "=f"(f.y) : "l"(v));
    return f;
}

// ---------------- scratch (device globals; zero-initialized) ---------------
__device__ float g_G0[(size_t)MROWS * NGP0];
__device__ float g_H0[(size_t)MROWS * UP0];
__device__ float g_G1[(size_t)MROWS * NGP1];
__device__ float g_H1[(size_t)MROWS * UP1];
__device__ float g_G2[(size_t)MROWS * NGP2];
__device__ float g_H2[(size_t)MROWS * UP2];

__device__ float g_Wx0[FIN0 * NGP0];
__device__ float g_Wh0[UP0 * NGP0];
__device__ float g_b0[NGP0];
__device__ float g_Wx1[FIN1 * NGP1];
__device__ float g_Wh1[UP1 * NGP1];
__device__ float g_b1[NGP1];
__device__ float g_Wx2[FIN2 * NGP2];
__device__ float g_Wh2[UP2 * NGP2];
__device__ float g_b2[NGP2];
__device__ float g_fcwT[32 * 32];

// ---------------------------------------------------------------------------
// Fused weight prep: all 3 layers + fc transpose in one kernel.
// Gate order n: [0,U)=ff1, [U,2U)=ff2, [2U,3U)=s(=ta+tb merged).
// ---------------------------------------------------------------------------
__device__ __forceinline__ void prep_dev(
    int U, int FIN, int NG, int NGP, int UP,
    const float* __restrict__ ff1w, const float* __restrict__ ff1b,
    const float* __restrict__ ff2w, const float* __restrict__ ff2b,
    const float* __restrict__ taw,  const float* __restrict__ tab,
    const float* __restrict__ tbw,  const float* __restrict__ tbb,
    const int*   __restrict__ mask,
    float* __restrict__ Wx, float* __restrict__ Wh, float* __restrict__ bias,
    int g0, int stride)
{
    const int C = FIN + U;
    for (int i = g0; i < FIN * NGP; i += stride) {
        int k = i / NGP, n = i % NGP;
        float v = 0.f;
        if (n < U)          v = ff1w[n * C + k] * (float)mask[n * C + k];
        else if (n < 2 * U) v = ff2w[(n - U) * C + k] * (float)mask[(n - U) * C + k];
        else if (n < NG)    v = taw[(n - 2 * U) * C + k] + tbw[(n - 2 * U) * C + k];
        Wx[i] = v;
    }
    for (int i = g0; i < UP * NGP; i += stride) {
        int k = i / NGP, n = i % NGP;
        float v = 0.f;
        if (k < U) {   // recurrent block of the NCP mask is all-ones
            if (n < U)          v = ff1w[n * C + FIN + k];
            else if (n < 2 * U) v = ff2w[(n - U) * C + FIN + k];
            else if (n < NG)    v = taw[(n - 2 * U) * C + FIN + k] + tbw[(n - 2 * U) * C + FIN + k];
        }
        Wh[i] = v;
    }
    for (int i = g0; i < NGP; i += stride) {
        float v = 0.f;
        if (i < U)          v = ff1b[i];
        else if (i < 2 * U) v = ff2b[i - U];
        else if (i < NG)    v = tab[i - 2 * U] + tbb[i - 2 * U];
        bias[i] = v;
    }
}

__global__ void prep_all(
    const float* f1w0, const float* f1b0, const float* f2w0, const float* f2b0,
    const float* taw0, const float* tab0, const float* tbw0, const float* tbb0,
    const int* m0,
    const float* f1w1, const float* f1b1, const float* f2w1, const float* f2b1,
    const float* taw1, const float* tab1, const float* tbw1, const float* tbb1,
    const int* m1,
    const float* f1w2, const float* f1b2, const float* f2w2, const float* f2b2,
    const float* taw2, const float* tab2, const float* tbw2, const float* tbb2,
    const int* m2,
    const float* fcw,
    float* Wx0, float* Wh0, float* B0,
    float* Wx1, float* Wh1, float* B1,
    float* Wx2, float* Wh2, float* B2,
    float* fcT)
{
    int g0 = blockIdx.x * blockDim.x + threadIdx.x;
    int st = gridDim.x * blockDim.x;
    prep_dev(U0, FIN0, NG0, NGP0, UP0, f1w0, f1b0, f2w0, f2b0, taw0, tab0, tbw0, tbb0,
             m0, Wx0, Wh0, B0, g0, st);
    prep_dev(U1, FIN1, NG1, NGP1, UP1, f1w1, f1b1, f2w1, f2b1, taw1, tab1, tbw1, tbb1,
             m1, Wx1, Wh1, B1, g0, st);
    prep_dev(U2, FIN2, NG2, NGP2, UP2, f1w2, f1b2, f2w2, f2b2, taw2, tab2, tbw2, tbb2,
             m2, Wx2, Wh2, B2, g0, st);
    if (g0 < 1024) {
        int o = g0 >> 5, k = g0 & 31;
        fcT[k * 32 + o] = fcw[o * 32 + k];
    }
}

// ---------------------------------------------------------------------------
// GEMM + bias with packed f32x2 FMA. BM=BN=64, BK=32, 128 threads,
// per-thread tile 4m x 8n. M % 64 == 0 always; N, lda multiples of 4.
// ---------------------------------------------------------------------------
__global__ __launch_bounds__(128)
void gemm_bias2(const float* __restrict__ A, int lda,
                const float* __restrict__ Bt, int ldb,
                const float* __restrict__ bias,
                float* __restrict__ C, int ldc,
                int N, int K) {
    __shared__ float sA[32][68];
    __shared__ float sB[32][68];
    const int bm = blockIdx.y * 64;
    const int bn = blockIdx.x * 64;
    const int tid = threadIdx.x;
    const int tm = (tid >> 3) << 2;
    const int tn = (tid & 7) << 3;
    ull acc[4][4];
#pragma unroll
    for (int i = 0; i < 4; ++i)
#pragma unroll
        for (int p = 0; p < 4; ++p) acc[i][p] = 0ull;

    for (int k0 = 0; k0 < K; k0 += 32) {
#pragma unroll
        for (int i = 0; i < 4; ++i) {
            int e = tid + i * 128;
            int m = e >> 3, k4 = (e & 7) << 2;
            const float* src = A + (size_t)(bm + m) * lda + k0 + k4;
            float4 v;
            if (k0 + k4 + 3 < K) {
                v = *(const float4*)src;
            } else {
                v.x = (k0 + k4     < K) ? src[0] : 0.f;
                v.y = (k0 + k4 + 1 < K) ? src[1] : 0.f;
                v.z = (k0 + k4 + 2 < K) ? src[2] : 0.f;
                v.w = 0.f;
            }
            sA[k4 + 0][m] = v.x; sA[k4 + 1][m] = v.y;
            sA[k4 + 2][m] = v.z; sA[k4 + 3][m] = v.w;
        }
#pragma unroll
        for (int i = 0; i < 4; ++i) {
            int e = tid + i * 128;
            int kk = e >> 4, n4 = (e & 15) << 2;
            float4 v = make_float4(0.f, 0.f, 0.f, 0.f);
            if (k0 + kk < K && bn + n4 < N)
                v = *(const float4*)(Bt + (size_t)(k0 + kk) * ldb + bn + n4);
            *(float4*)&sB[kk][n4] = v;
        }
        __syncthreads();
#pragma unroll
        for (int kk = 0; kk < 32; ++kk) {
            float4 a = *(const float4*)&sA[kk][tm];
            ulonglong2 bl = *(const ulonglong2*)&sB[kk][tn];
            ulonglong2 bh = *(const ulonglong2*)&sB[kk][tn + 4];
            ull d0 = fdup(a.x), d1 = fdup(a.y), d2 = fdup(a.z), d3 = fdup(a.w);
            acc[0][0] = ffma2(d0, bl.x, acc[0][0]);
            acc[1][0] = ffma2(d1, bl.x, acc[1][0]);
            acc[2][0] = ffma2(d2, bl.x, acc[2][0]);
            acc[3][0] = ffma2(d3, bl.x, acc[3][0]);
            acc[0][1] = ffma2(d0, bl.y, acc[0][1]);
            acc[1][1] = ffma2(d1, bl.y, acc[1][1]);
            acc[2][1] = ffma2(d2, bl.y, acc[2][1]);
            acc[3][1] = ffma2(d3, bl.y, acc[3][1]);
            acc[0][2] = ffma2(d0, bh.x, acc[0][2]);
            acc[1][2] = ffma2(d1, bh.x, acc[1][2]);
            acc[2][2] = ffma2(d2, bh.x, acc[2][2]);
            acc[3][2] = ffma2(d3, bh.x, acc[3][2]);
            acc[0][3] = ffma2(d0, bh.y, acc[0][3]);
            acc[1][3] = ffma2(d1, bh.y, acc[1][3]);
            acc[2][3] = ffma2(d2, bh.y, acc[2][3]);
            acc[3][3] = ffma2(d3, bh.y, acc[3][3]);
        }
        __syncthreads();
    }
#pragma unroll
    for (int i = 0; i < 4; ++i) {
        float* crow = C + (size_t)(bm + tm + i) * ldc + bn + tn;
#pragma unroll
        for (int p = 0; p < 4; ++p) {
            int n = bn + tn + 2 * p;
            if (n < N) {
                float2 f = funpack(acc[i][p]);
                f.x += bias[n];
                f.y += bias[n + 1];
                *(float2*)(crow + 2 * p) = f;
            }
        }
    }
}

// ---------------------------------------------------------------------------
// Recurrent pass, hybrid register/SMEM weights.
//  * TN cols per thread, NSPLIT-way k-split (SMEM reduction between groups).
//  * Per group: first KR k-slices from registers, remaining KS from SMEM
//    (per-thread private row).
//  * h kept DUPLICATED as f32x2 in SMEM -> matvec inner loop is
//    LDS.128 + fma.rn.f32x2 only. 2 batch rows per CTA.
// ---------------------------------------------------------------------------
template<int U, int UP, int NGP, int TN, int NSPLIT, int KR, int THREADS>
__global__ __launch_bounds__(THREADS, 1)
void rec_hyb(const float* __restrict__ G, const float* __restrict__ Wg,
             float* __restrict__ H) {
    constexpr int NP = TN / 2;
    constexpr int P = NGP / TN;
    constexpr int KH = UP / NSPLIT;
    constexpr int KS = KH - KR;
    constexpr int MT = P * NSPLIT;
    constexpr int ROWU = KS * NP + 2;                       // ulls per sW row
    constexpr int REDN = (NSPLIT > 1) ? (NSPLIT - 1) * P * 2 * NP : 0;

    extern __shared__ __align__(16) unsigned char dynsmem[];
    ull* sW   = (ull*)dynsmem;                              // [MT][ROWU]
    ull* shd  = sW + (size_t)MT * ROWU;                     // [2][UP] dup'd h
    ull* sred = shd + 2 * UP;                               // [REDN]
    float* sg = (float*)(sred + REDN);                      // [2][NGP]

    const int tid = threadIdx.x;
    const bool mv = tid < MT;
    const int s = mv ? (tid / P) : 0;
    const int cg = tid % P;
    const int n0 = cg * TN;
    const int kbase = s * KH;
    const bool lead = tid < P;

    // register-resident weight slice
    ull w[KR * NP];
#pragma unroll
    for (int j = 0; j < KR; ++j)
#pragma unroll
        for (int p = 0; p < NP; ++p) {
            float2 wv = *(const float2*)&Wg[(size_t)(kbase + j) * NGP + n0 + 2 * p];
            w[j * NP + p] = fpack(wv.x, wv.y);
        }
    // SMEM-resident weight slice (thread-private row)
    ull* wsp = sW + (size_t)tid * ROWU;
    if (mv) {
#pragma unroll
        for (int j = 0; j < KS; ++j)
#pragma unroll
            for (int p = 0; p < NP; ++p) {
                float2 wv = *(const float2*)&Wg[(size_t)(kbase + KR + j) * NGP + n0 + 2 * p];
                wsp[j * NP + p] = fpack(wv.x, wv.y);
            }
    }
    for (int i = tid; i < 2 * UP; i += THREADS) shd[i] = 0ull;
    __syncthreads();

    const size_t bb0 = (size_t)blockIdx.x * 2;
    const float* Gp = G + bb0 * TSTEPS * NGP + n0;
    const size_t GOFF = (size_t)TSTEPS * NGP;
    float* Hp = H + bb0 * TSTEPS * UP;

    for (int t = 0; t < TSTEPS; ++t) {
        float gav[TN], gbv[TN];
        if (lead) {                    // issued early, consumed after matvec
            if constexpr (TN == 4) {
                float4 a = *(const float4*)Gp;
                float4 b = *(const float4*)(Gp + GOFF);
                gav[0] = a.x; gav[1] = a.y; gav[2] = a.z; gav[3] = a.w;
                gbv[0] = b.x; gbv[1] = b.y; gbv[2] = b.z; gbv[3] = b.w;
            } else {
                float2 a = *(const float2*)Gp;
                float2 b = *(const float2*)(Gp + GOFF);
                gav[0] = a.x; gav[1] = a.y;
                gbv[0] = b.x; gbv[1] = b.y;
            }
        }

        ull acc[2][NP][2];
#pragma unroll
        for (int b = 0; b < 2; ++b)
#pragma unroll
            for (int p = 0; p < NP; ++p) { acc[b][p][0] = 0ull; acc[b][p][1] = 0ull; }

        if (mv) {
#pragma unroll
            for (int j = 0; j < KR; j += 2) {        // register weights
                ulonglong2 h0 = *(const ulonglong2*)&shd[0 * UP + kbase + j];
                ulonglong2 h1 = *(const ulonglong2*)&shd[1 * UP + kbase + j];
#pragma unroll
                for (int p = 0; p < NP; ++p) {
                    acc[0][p][0] = ffma2(w[j * NP + p],       h0.x, acc[0][p][0]);
                    acc[0][p][1] = ffma2(w[(j + 1) * NP + p], h0.y, acc[0][p][1]);
                    acc[1][p][0] = ffma2(w[j * NP + p],       h1.x, acc[1][p][0]);
                    acc[1][p][1] = ffma2(w[(j + 1) * NP + p], h1.y, acc[1][p][1]);
                }
            }
#pragma unroll
            for (int j = 0; j < KS; j += 2) {        // SMEM weights
                ulonglong2 h0 = *(const ulonglong2*)&shd[0 * UP + kbase + KR + j];
                ulonglong2 h1 = *(const ulonglong2*)&shd[1 * UP + kbase + KR + j];
#pragma unroll
                for (int p = 0; p < NP; ++p) {
                    ull wa = wsp[j * NP + p];
                    ull wb = wsp[(j + 1) * NP + p];
                    acc[0][p][0] = ffma2(wa, h0.x, acc[0][p][0]);
                    acc[0][p][1] = ffma2(wb, h0.y, acc[0][p][1]);
                    acc[1][p][0] = ffma2(wa, h1.x, acc[1][p][0]);
                    acc[1][p][1] = ffma2(wb, h1.y, acc[1][p][1]);
                }
            }
            if (s > 0) {
#pragma unroll
                for (int b = 0; b < 2; ++b)
#pragma unroll
                    for (int p = 0; p < NP; ++p)
                        sred[((s - 1) * P + cg) * 2 * NP + b * NP + p] =
                            fadd2(acc[b][p][0], acc[b][p][1]);
            }
        }
        __syncthreads();
        if (lead) {
#pragma unroll
            for (int b = 0; b < 2; ++b)
#pragma unroll
                for (int p = 0; p < NP; ++p) {
                    ull v = fadd2(acc[b][p][0], acc[b][p][1]);
#pragma unroll
                    for (int s2 = 1; s2 < NSPLIT; ++s2)
                        v = fadd2(v, sred[((s2 - 1) * P + cg) * 2 * NP + b * NP + p]);
                    float2 f = funpack(v);
                    float ge = b ? gbv[2 * p] : gav[2 * p];
                    float go = b ? gbv[2 * p + 1] : gav[2 * p + 1];
                    sg[b * NGP + n0 + 2 * p]     = f.x + ge;
                    sg[b * NGP + n0 + 2 * p + 1] = f.y + go;
                }
        }
        __syncthreads();
        for (int i = tid; i < 2 * U; i += THREADS) {
            int bb = (i >= U) ? 1 : 0;
            int u = i - bb * U;
            float f1 = tanhf(sg[bb * NGP + u]);
            float f2 = tanhf(sg[bb * NGP + u + U]);
            float sv = sg[bb * NGP + u + 2 * U];
            float sig = 1.f / (1.f + __expf(-sv));
            float hn = f1 + sig * (f2 - f1);
            Hp[((size_t)bb * TSTEPS + t) * UP + u] = hn;
            shd[bb * UP + u] = fdup(hn);
        }
        __syncthreads();
        Gp += NGP;
    }
}

// rec configs
#define R0_TN 4
#define R0_NS 2
#define R0_KR 40
#define R0_TH 256
#define R1_TN 2
#define R1_NS 2
#define R1_KR 48
#define R1_TH 288
#define R2_TN 2
#define R2_NS 1
#define R2_KR 32
#define R2_TH 96

static size_t rec_sm(int NGP, int UP, int TN, int NSPLIT, int KR) {
    int NP = TN / 2, P = NGP / TN;
    int KH = UP / NSPLIT, KS = KH - KR;
    int MT = P * NSPLIT;
    size_t rowu = (size_t)KS * NP + 2;
    size_t red = (NSPLIT > 1) ? (size_t)(NSPLIT - 1) * P * 2 * NP : 0;
    return ((size_t)MT * rowu + 2 * (size_t)UP + red) * 8 + (size_t)2 * NGP * 4;
}

// ---------------------------------------------------------------------------
// host side
// ---------------------------------------------------------------------------
static float* dev_addr(const void* sym) {
    void* p = nullptr;
    cudaGetSymbolAddress(&p, sym);
    return (float*)p;
}

extern "C" void kernel_launch(void* const* d_in, const int* in_sizes, int n_in,
                              void* d_out, int out_size) {
    // Resolve input ordering: dict order has mask0 (35505 ints) at index 9,
    // signature order has l1_ff1_w (19936 floats) there.
    int L0 = 1, M0, L1, M1, L2, M2, FCW, FCB;
    if (in_sizes[9] == 19936) {            // signature order
        L1 = 9; L2 = 17; FCW = 25; FCB = 26; M0 = 27; M1 = 28; M2 = 29;
    } else {                               // dict order
        M0 = 9; L1 = 10; M1 = 18; L2 = 19; M2 = 27; FCW = 28; FCB = 29;
    }

    const float* X = (const float*)d_in[0];
    float* OUT = (float*)d_out;

    float* G0 = dev_addr(g_G0); float* H0 = dev_addr(g_H0);
    float* G1 = dev_addr(g_G1); float* H1 = dev_addr(g_H1);
    float* G2 = dev_addr(g_G2); float* H2 = dev_addr(g_H2);
    float* Wx0 = dev_addr(g_Wx0); float* Wh0 = dev_addr(g_Wh0); float* B0 = dev_addr(g_b0);
    float* Wx1 = dev_addr(g_Wx1); float* Wh1 = dev_addr(g_Wh1); float* B1 = dev_addr(g_b1);
    float* Wx2 = dev_addr(g_Wx2); float* Wh2 = dev_addr(g_Wh2); float* B2 = dev_addr(g_b2);
    float* FcT = dev_addr(g_fcwT);

    size_t sm0 = rec_sm(NGP0, UP0, R0_TN, R0_NS, R0_KR);
    size_t sm1 = rec_sm(NGP1, UP1, R1_TN, R1_NS, R1_KR);
    size_t sm2 = rec_sm(NGP2, UP2, R2_TN, R2_NS, R2_KR);
    cudaFuncSetAttribute((const void*)rec_hyb<U0, UP0, NGP0, R0_TN, R0_NS, R0_KR, R0_TH>,
                         cudaFuncAttributeMaxDynamicSharedMemorySize, (int)sm0);
    cudaFuncSetAttribute((const void*)rec_hyb<U1, UP1, NGP1, R1_TN, R1_NS, R1_KR, R1_TH>,
                         cudaFuncAttributeMaxDynamicSharedMemorySize, (int)sm1);
    cudaFuncSetAttribute((const void*)rec_hyb<U2, UP2, NGP2, R2_TN, R2_NS, R2_KR, R2_TH>,
                         cudaFuncAttributeMaxDynamicSharedMemorySize, (int)sm2);

    // ---- fused weight prep (1 launch) ----
    prep_all<<<512, 256>>>(
        (const float*)d_in[L0 + 0], (const float*)d_in[L0 + 1],
        (const float*)d_in[L0 + 2], (const float*)d_in[L0 + 3],
        (const float*)d_in[L0 + 4], (const float*)d_in[L0 + 5],
        (const float*)d_in[L0 + 6], (const float*)d_in[L0 + 7],
        (const int*)d_in[M0],
        (const float*)d_in[L1 + 0], (const float*)d_in[L1 + 1],
        (const float*)d_in[L1 + 2], (const float*)d_in[L1 + 3],
        (const float*)d_in[L1 + 4], (const float*)d_in[L1 + 5],
        (const float*)d_in[L1 + 6], (const float*)d_in[L1 + 7],
        (const int*)d_in[M1],
        (const float*)d_in[L2 + 0], (const float*)d_in[L2 + 1],
        (const float*)d_in[L2 + 2], (const float*)d_in[L2 + 3],
        (const float*)d_in[L2 + 4], (const float*)d_in[L2 + 5],
        (const float*)d_in[L2 + 6], (const float*)d_in[L2 + 7],
        (const int*)d_in[M2],
        (const float*)d_in[FCW],
        Wx0, Wh0, B0, Wx1, Wh1, B1, Wx2, Wh2, B2, FcT);

    const int MB = MROWS / 64;   // 4096

    // ---- layer 0 ----
    gemm_bias2<<<dim3((NGP0 + 63) / 64, MB), 128>>>(X, FIN0, Wx0, NGP0, B0, G0, NGP0, NGP0, FIN0);
    rec_hyb<U0, UP0, NGP0, R0_TN, R0_NS, R0_KR, R0_TH>
        <<<NBATCH / 2, R0_TH, sm0>>>(G0, Wh0, H0);
    // ---- layer 1 ----
    gemm_bias2<<<dim3((NGP1 + 63) / 64, MB), 128>>>(H0, UP0, Wx1, NGP1, B1, G1, NGP1, NGP1, U0);
    rec_hyb<U1, UP1, NGP1, R1_TN, R1_NS, R1_KR, R1_TH>
        <<<NBATCH / 2, R1_TH, sm1>>>(G1, Wh1, H1);
    // ---- layer 2 ----
    gemm_bias2<<<dim3((NGP2 + 63) / 64, MB), 128>>>(H1, UP1, Wx2, NGP2, B2, G2, NGP2, NGP2, U1);
    rec_hyb<U2, UP2, NGP2, R2_TN, R2_NS, R2_KR, R2_TH>
        <<<NBATCH / 2, R2_TH, sm2>>>(G2, Wh2, H2);
    // ---- final FC (adaptive pool is identity since MOT == OUT) ----
    gemm_bias2<<<dim3(1, MB), 128>>>(H2, UP2, FcT, 32, (const float*)d_in[FCB], OUT, 32, 32, 32);
}